// round 15
// baseline (speedup 1.0000x reference)
#include <cuda_runtime.h>
#include <cuda_bf16.h>

// SuctionNet fused persistent kernel (single launch):
//   P0: zero used-voxel bitmap
//   P1: mark used[idx[p]] = 1
//   P2: scores[v] = (w0.feats[v]+b0, w1.feats[v]+b1) for USED voxels only,
//       streaming the table with per-row predicated loads (~26% traffic cut)
//   P3: out[p] = scores[idx[p]]  (L2-warm 1.2MB table)
// Phases separated by a sense-reversing software grid barrier; grid is
// 148 SMs x 3 blocks, co-residency forced via __launch_bounds__(256,3).

#define FEAT_DIM 256
#define NV_MAX 150016
#define FULL 0xFFFFFFFFu
#define NBLOCKS 444
#define NTHREADS (NBLOCKS * 256)

__device__ float2 g_scores[NV_MAX];
__device__ unsigned char g_used[NV_MAX];
__device__ unsigned int g_cnt;    // barrier arrival count (returns to 0)
__device__ unsigned int g_flag;   // barrier sense (persists; sense-reversal)

__device__ __forceinline__ void grid_barrier(unsigned int* sense)
{
    __syncthreads();
    if (threadIdx.x == 0) {
        const unsigned int target = *sense ^ 1u;
        __threadfence();
        const unsigned int a = atomicAdd(&g_cnt, 1u);
        if (a == NBLOCKS - 1u) {
            g_cnt = 0u;
            __threadfence();
            atomicExch(&g_flag, target);      // release
        } else {
            while (*(volatile unsigned int*)&g_flag != target) { }
            __threadfence();
        }
    }
    *sense ^= 1u;
    __syncthreads();
}

__device__ __forceinline__ float dot4(const float4 a, const float4 w) {
    float s = a.x * w.x;
    s = fmaf(a.y, w.y, s);
    s = fmaf(a.z, w.z, s);
    s = fmaf(a.w, w.w, s);
    return s;
}

__global__ void __launch_bounds__(256, 3)
fused_suction(const float* __restrict__ feats,
              const int* __restrict__ idx,
              const float* __restrict__ w,
              const float* __restrict__ bias,
              float* __restrict__ out,
              int nv, int n)
{
    const int tid  = blockIdx.x * blockDim.x + threadIdx.x;
    const int lane = threadIdx.x & 31;
    const int m    = lane & 15;
    const int h    = lane >> 4;
    const int warp = tid >> 5;
    const int nwarps = NTHREADS / 32;

    unsigned int sense = *(volatile unsigned int*)&g_flag;  // initial sense

    // ---- P0: zero bitmap (16B stores) ----
    for (int i = tid; i < NV_MAX / 16; i += NTHREADS)
        reinterpret_cast<uint4*>(g_used)[i] = make_uint4(0u, 0u, 0u, 0u);
    grid_barrier(&sense);

    // ---- P1: mark used voxels ----
    for (int p = tid; p < n; p += NTHREADS)
        g_used[__ldg(idx + p)] = 1;
    grid_barrier(&sense);

    // ---- P2: streaming GEMV over used voxels ----
    {
        const float4* w0f = reinterpret_cast<const float4*>(w);
        const float4* w1f = reinterpret_cast<const float4*>(w + FEAT_DIM);
        float4 w0[4], w1[4];
        #pragma unroll
        for (int i = 0; i < 4; i++) {
            w0[i] = __ldg(w0f + 16 * i + m);
            w1[i] = __ldg(w1f + 16 * i + m);
        }
        const float bsel = (m < 8) ? __ldg(bias) : __ldg(bias + 1);
        const float4 z4 = make_float4(0.f, 0.f, 0.f, 0.f);

        const int ntiles = (nv + 31) / 32;
        for (int t = warp; t < ntiles; t += nwarps) {
            const int base = t * 32;
            const int fv = base + lane;
            const unsigned int myflag =
                (fv < nv) ? (unsigned int)g_used[fv] : 0u;   // coalesced 32B

            #pragma unroll
            for (int j0 = 0; j0 < 32; j0 += 4) {
                const int vA = base + j0 + h;
                const int vB = base + j0 + 2 + h;
                const unsigned int fA = __shfl_sync(FULL, myflag, j0 + h);
                const unsigned int fB = __shfl_sync(FULL, myflag, j0 + 2 + h);

                const float4* rA = reinterpret_cast<const float4*>(
                    feats + (size_t)(vA < nv ? vA : 0) * FEAT_DIM);
                const float4* rB = reinterpret_cast<const float4*>(
                    feats + (size_t)(vB < nv ? vB : 0) * FEAT_DIM);

                // Predicated loads: unreferenced rows issue no requests.
                const float4 a0 = fA ? __ldg(rA + m)      : z4;
                const float4 a1 = fA ? __ldg(rA + 16 + m) : z4;
                const float4 a2 = fA ? __ldg(rA + 32 + m) : z4;
                const float4 a3 = fA ? __ldg(rA + 48 + m) : z4;
                const float4 c0 = fB ? __ldg(rB + m)      : z4;
                const float4 c1 = fB ? __ldg(rB + 16 + m) : z4;
                const float4 c2 = fB ? __ldg(rB + 32 + m) : z4;
                const float4 c3 = fB ? __ldg(rB + 48 + m) : z4;

                {   // pair A
                    float s0 = dot4(a0, w0[0]) + dot4(a1, w0[1]) + dot4(a2, w0[2]) + dot4(a3, w0[3]);
                    float s1 = dot4(a0, w1[0]) + dot4(a1, w1[1]) + dot4(a2, w1[2]) + dot4(a3, w1[3]);
                    const float t0 = __shfl_xor_sync(FULL, s0, 8);
                    const float t1 = __shfl_xor_sync(FULL, s1, 8);
                    float acc = (m < 8) ? (s0 + t0) : (s1 + t1);
                    acc += __shfl_xor_sync(FULL, acc, 4);
                    acc += __shfl_xor_sync(FULL, acc, 2);
                    acc += __shfl_xor_sync(FULL, acc, 1);
                    if (fA && vA < nv) {
                        if (m == 0) g_scores[vA].x = acc + bsel;
                        if (m == 8) g_scores[vA].y = acc + bsel;
                    }
                }
                {   // pair B
                    float s0 = dot4(c0, w0[0]) + dot4(c1, w0[1]) + dot4(c2, w0[2]) + dot4(c3, w0[3]);
                    float s1 = dot4(c0, w1[0]) + dot4(c1, w1[1]) + dot4(c2, w1[2]) + dot4(c3, w1[3]);
                    const float t0 = __shfl_xor_sync(FULL, s0, 8);
                    const float t1 = __shfl_xor_sync(FULL, s1, 8);
                    float acc = (m < 8) ? (s0 + t0) : (s1 + t1);
                    acc += __shfl_xor_sync(FULL, acc, 4);
                    acc += __shfl_xor_sync(FULL, acc, 2);
                    acc += __shfl_xor_sync(FULL, acc, 1);
                    if (fB && vB < nv) {
                        if (m == 0) g_scores[vB].x = acc + bsel;
                        if (m == 8) g_scores[vB].y = acc + bsel;
                    }
                }
            }
        }
    }
    grid_barrier(&sense);

    // ---- P3: scatter (scores table is L2-resident) ----
    for (int p = tid; p < n; p += NTHREADS) {
        const float2 s = g_scores[__ldg(idx + p)];
        out[p]     = s.x;
        out[n + p] = s.y;
    }
}

extern "C" void kernel_launch(void* const* d_in, const int* in_sizes, int n_in,
                              void* d_out, int out_size)
{
    const float* feats = (const float*)d_in[0];      // [150000*256]
    const int*   idx   = (const int*)d_in[1];        // [200000] int32
    const float* w     = (const float*)d_in[2];      // [2*256]
    const float* b     = (const float*)d_in[3];      // [2]
    float* out = (float*)d_out;                      // [2 * n]

    const int nv = in_sizes[0] / FEAT_DIM;           // 150000
    const int n  = in_sizes[1];                      // 200000

    fused_suction<<<NBLOCKS, 256>>>(feats, idx, w, b, out, nv, n);
}

// round 16
// speedup vs baseline: 1.4451x; 1.4451x over previous
#include <cuda_runtime.h>
#include <cuda_bf16.h>

// SuctionNet two-phase:
//   Phase 1: scores[v] = (w0.feats[v]+b0, w1.feats[v]+b1) for all voxels,
//            streaming the 153.6MB table sequentially with __ldcs
//            (evict-first: zero-reuse stream must NOT evict the score table
//            from L2). 16 lanes per voxel, 16-voxel tiles -> 9375 warps.
//   Phase 2: out[p] = scores[idx[p]], 1 point/thread (200k threads);
//            gathers now hit the L2-resident 1.2MB score table.

#define FEAT_DIM 256
#define NV_MAX 150016
#define FULL 0xFFFFFFFFu

__device__ float2 g_scores[NV_MAX];

__device__ __forceinline__ float dot4(const float4 a, const float4 w) {
    float s = a.x * w.x;
    s = fmaf(a.y, w.y, s);
    s = fmaf(a.z, w.z, s);
    s = fmaf(a.w, w.w, s);
    return s;
}

__global__ __launch_bounds__(128)
void score_voxels(const float* __restrict__ feats,
                  const float* __restrict__ w,
                  const float* __restrict__ bias,
                  int nv)
{
    const int lane = threadIdx.x & 31;
    const int m    = lane & 15;          // sublane within 16-lane group
    const int h    = lane >> 4;          // half-warp: 0 or 1
    const int warp = (blockIdx.x * blockDim.x + threadIdx.x) >> 5;
    const int base = warp * 16;          // 16 voxels per warp
    if (base >= nv) return;

    // Weight slice for lane m: float4 indices {m, 16+m, 32+m, 48+m}.
    const float4* w0f = reinterpret_cast<const float4*>(w);
    const float4* w1f = reinterpret_cast<const float4*>(w + FEAT_DIM);
    float4 w0[4], w1[4];
    #pragma unroll
    for (int i = 0; i < 4; i++) {
        w0[i] = __ldg(w0f + 16 * i + m);
        w1[i] = __ldg(w1f + 16 * i + m);
    }
    const float bsel = (m < 8) ? __ldg(bias) : __ldg(bias + 1);

    #pragma unroll
    for (int j0 = 0; j0 < 16; j0 += 4) {
        const int vA = base + j0 + h;         // rows j0, j0+1
        const int vB = base + j0 + 2 + h;     // rows j0+2, j0+3
        const float4* rA = reinterpret_cast<const float4*>(
            feats + (size_t)(vA < nv ? vA : 0) * FEAT_DIM);
        const float4* rB = reinterpret_cast<const float4*>(
            feats + (size_t)(vB < nv ? vB : 0) * FEAT_DIM);

        // 8 independent LDG.128.CS — evict-first streaming loads.
        const float4 a0 = __ldcs(rA + m);
        const float4 a1 = __ldcs(rA + 16 + m);
        const float4 a2 = __ldcs(rA + 32 + m);
        const float4 a3 = __ldcs(rA + 48 + m);
        const float4 c0 = __ldcs(rB + m);
        const float4 c1 = __ldcs(rB + 16 + m);
        const float4 c2 = __ldcs(rB + 32 + m);
        const float4 c3 = __ldcs(rB + 48 + m);

        {   // pair A (voxels base+j0, base+j0+1)
            float s0 = dot4(a0, w0[0]) + dot4(a1, w0[1]) + dot4(a2, w0[2]) + dot4(a3, w0[3]);
            float s1 = dot4(a0, w1[0]) + dot4(a1, w1[1]) + dot4(a2, w1[2]) + dot4(a3, w1[3]);
            const float t0 = __shfl_xor_sync(FULL, s0, 8);
            const float t1 = __shfl_xor_sync(FULL, s1, 8);
            float acc = (m < 8) ? (s0 + t0) : (s1 + t1);
            acc += __shfl_xor_sync(FULL, acc, 4);
            acc += __shfl_xor_sync(FULL, acc, 2);
            acc += __shfl_xor_sync(FULL, acc, 1);
            if (vA < nv) {
                if (m == 0) g_scores[vA].x = acc + bsel;   // lanes 0,16
                if (m == 8) g_scores[vA].y = acc + bsel;   // lanes 8,24
            }
        }
        {   // pair B (voxels base+j0+2, base+j0+3)
            float s0 = dot4(c0, w0[0]) + dot4(c1, w0[1]) + dot4(c2, w0[2]) + dot4(c3, w0[3]);
            float s1 = dot4(c0, w1[0]) + dot4(c1, w1[1]) + dot4(c2, w1[2]) + dot4(c3, w1[3]);
            const float t0 = __shfl_xor_sync(FULL, s0, 8);
            const float t1 = __shfl_xor_sync(FULL, s1, 8);
            float acc = (m < 8) ? (s0 + t0) : (s1 + t1);
            acc += __shfl_xor_sync(FULL, acc, 4);
            acc += __shfl_xor_sync(FULL, acc, 2);
            acc += __shfl_xor_sync(FULL, acc, 1);
            if (vB < nv) {
                if (m == 0) g_scores[vB].x = acc + bsel;
                if (m == 8) g_scores[vB].y = acc + bsel;
            }
        }
    }
}

__global__ __launch_bounds__(256)
void scatter_scores(const int* __restrict__ idx,
                    float* __restrict__ out,
                    int n)
{
    const int p = blockIdx.x * blockDim.x + threadIdx.x;
    if (p < n) {
        const int v = __ldg(idx + p);
        const float2 s = g_scores[v];   // L2-resident 1.2MB table
        out[p]     = s.x;
        out[n + p] = s.y;
    }
}

extern "C" void kernel_launch(void* const* d_in, const int* in_sizes, int n_in,
                              void* d_out, int out_size)
{
    const float* feats = (const float*)d_in[0];      // [150000*256]
    const int*   idx   = (const int*)d_in[1];        // [200000] int32
    const float* w     = (const float*)d_in[2];      // [2*256]
    const float* b     = (const float*)d_in[3];      // [2]
    float* out = (float*)d_out;                      // [2 * n]

    const int nv = in_sizes[0] / FEAT_DIM;           // 150000 voxels
    const int n  = in_sizes[1];                      // 200000 points

    // Phase 1: 16 voxels/warp -> 9375 warps.
    const int warps1  = (nv + 15) / 16;              // 9375
    const int blocks1 = (warps1 + 3) / 4;            // 2344 (128 thr = 4 warps)
    score_voxels<<<blocks1, 128>>>(feats, w, b, nv);

    // Phase 2: 1 point/thread.
    const int blocks2 = (n + 255) / 256;             // 782
    scatter_scores<<<blocks2, 256>>>(idx, out, n);
}

// round 17
// speedup vs baseline: 1.5332x; 1.0609x over previous
#include <cuda_runtime.h>
#include <cuda_bf16.h>

// SuctionNet two-phase + PDL overlap:
//   Phase 1: scores[v] = (w0.feats[v]+b0, w1.feats[v]+b1) streaming the
//            153.6MB table with __ldcs (evict-first keeps score table in L2).
//            16 lanes/voxel, 16-voxel tiles (9375 warps). ~6.4 TB/s.
//   Phase 2: out[p] = scores[idx[p]] — launched with Programmatic Dependent
//            Launch: blocks spin up during phase-1 drain, prefetch idx,
//            then cudaGridDependencySynchronize() before reading scores.

#define FEAT_DIM 256
#define NV_MAX 150016
#define FULL 0xFFFFFFFFu

__device__ float2 g_scores[NV_MAX];

__device__ __forceinline__ float dot4(const float4 a, const float4 w) {
    float s = a.x * w.x;
    s = fmaf(a.y, w.y, s);
    s = fmaf(a.z, w.z, s);
    s = fmaf(a.w, w.w, s);
    return s;
}

__global__ __launch_bounds__(128)
void score_voxels(const float* __restrict__ feats,
                  const float* __restrict__ w,
                  const float* __restrict__ bias,
                  int nv)
{
    const int lane = threadIdx.x & 31;
    const int m    = lane & 15;          // sublane within 16-lane group
    const int h    = lane >> 4;          // half-warp: 0 or 1
    const int warp = (blockIdx.x * blockDim.x + threadIdx.x) >> 5;
    const int base = warp * 16;          // 16 voxels per warp

    if (base < nv) {
        // Weight slice for lane m: float4 indices {m, 16+m, 32+m, 48+m}.
        const float4* w0f = reinterpret_cast<const float4*>(w);
        const float4* w1f = reinterpret_cast<const float4*>(w + FEAT_DIM);
        float4 w0[4], w1[4];
        #pragma unroll
        for (int i = 0; i < 4; i++) {
            w0[i] = __ldg(w0f + 16 * i + m);
            w1[i] = __ldg(w1f + 16 * i + m);
        }
        const float bsel = (m < 8) ? __ldg(bias) : __ldg(bias + 1);

        #pragma unroll
        for (int j0 = 0; j0 < 16; j0 += 4) {
            const int vA = base + j0 + h;
            const int vB = base + j0 + 2 + h;
            const float4* rA = reinterpret_cast<const float4*>(
                feats + (size_t)(vA < nv ? vA : 0) * FEAT_DIM);
            const float4* rB = reinterpret_cast<const float4*>(
                feats + (size_t)(vB < nv ? vB : 0) * FEAT_DIM);

            // 8 independent LDG.128.CS — evict-first streaming loads.
            const float4 a0 = __ldcs(rA + m);
            const float4 a1 = __ldcs(rA + 16 + m);
            const float4 a2 = __ldcs(rA + 32 + m);
            const float4 a3 = __ldcs(rA + 48 + m);
            const float4 c0 = __ldcs(rB + m);
            const float4 c1 = __ldcs(rB + 16 + m);
            const float4 c2 = __ldcs(rB + 32 + m);
            const float4 c3 = __ldcs(rB + 48 + m);

            {   // pair A
                float s0 = dot4(a0, w0[0]) + dot4(a1, w0[1]) + dot4(a2, w0[2]) + dot4(a3, w0[3]);
                float s1 = dot4(a0, w1[0]) + dot4(a1, w1[1]) + dot4(a2, w1[2]) + dot4(a3, w1[3]);
                const float t0 = __shfl_xor_sync(FULL, s0, 8);
                const float t1 = __shfl_xor_sync(FULL, s1, 8);
                float acc = (m < 8) ? (s0 + t0) : (s1 + t1);
                acc += __shfl_xor_sync(FULL, acc, 4);
                acc += __shfl_xor_sync(FULL, acc, 2);
                acc += __shfl_xor_sync(FULL, acc, 1);
                if (vA < nv) {
                    if (m == 0) g_scores[vA].x = acc + bsel;
                    if (m == 8) g_scores[vA].y = acc + bsel;
                }
            }
            {   // pair B
                float s0 = dot4(c0, w0[0]) + dot4(c1, w0[1]) + dot4(c2, w0[2]) + dot4(c3, w0[3]);
                float s1 = dot4(c0, w1[0]) + dot4(c1, w1[1]) + dot4(c2, w1[2]) + dot4(c3, w1[3]);
                const float t0 = __shfl_xor_sync(FULL, s0, 8);
                const float t1 = __shfl_xor_sync(FULL, s1, 8);
                float acc = (m < 8) ? (s0 + t0) : (s1 + t1);
                acc += __shfl_xor_sync(FULL, acc, 4);
                acc += __shfl_xor_sync(FULL, acc, 2);
                acc += __shfl_xor_sync(FULL, acc, 1);
                if (vB < nv) {
                    if (m == 0) g_scores[vB].x = acc + bsel;
                    if (m == 8) g_scores[vB].y = acc + bsel;
                }
            }
        }
    }

#if __CUDA_ARCH__ >= 900
    // Allow the dependent scatter kernel to begin launching.
    cudaTriggerProgrammaticLaunchCompletion();
#endif
}

__global__ __launch_bounds__(256)
void scatter_scores(const int* __restrict__ idx,
                    float* __restrict__ out,
                    int n)
{
    const int p = blockIdx.x * blockDim.x + threadIdx.x;
    // Prefetch index — independent of phase-1 results.
    int v = 0;
    if (p < n) v = __ldg(idx + p);

#if __CUDA_ARCH__ >= 900
    // Wait until score_voxels has fully completed (memory visible).
    cudaGridDependencySynchronize();
#endif

    if (p < n) {
        const float2 s = g_scores[v];   // L2-resident score table
        out[p]     = s.x;
        out[n + p] = s.y;
    }
}

extern "C" void kernel_launch(void* const* d_in, const int* in_sizes, int n_in,
                              void* d_out, int out_size)
{
    const float* feats = (const float*)d_in[0];      // [150000*256]
    const int*   idx   = (const int*)d_in[1];        // [200000] int32
    const float* w     = (const float*)d_in[2];      // [2*256]
    const float* b     = (const float*)d_in[3];      // [2]
    float* out = (float*)d_out;                      // [2 * n]

    const int nv = in_sizes[0] / FEAT_DIM;           // 150000 voxels
    const int n  = in_sizes[1];                      // 200000 points

    // Phase 1: 16 voxels/warp -> 9375 warps.
    const int warps1  = (nv + 15) / 16;              // 9375
    const int blocks1 = (warps1 + 3) / 4;            // 2344
    score_voxels<<<blocks1, 128>>>(feats, w, b, nv);

    // Phase 2: PDL — overlap ramp + idx load with phase-1 drain.
    const int blocks2 = (n + 255) / 256;             // 782
    cudaLaunchConfig_t cfg = {};
    cfg.gridDim  = dim3(blocks2, 1, 1);
    cfg.blockDim = dim3(256, 1, 1);
    cfg.dynamicSmemBytes = 0;
    cfg.stream = 0;                                  // legacy stream (captured)
    cudaLaunchAttribute attr[1];
    attr[0].id = cudaLaunchAttributeProgrammaticStreamSerialization;
    attr[0].val.programmaticStreamSerializationAllowed = 1;
    cfg.attrs = attr;
    cfg.numAttrs = 1;
    cudaLaunchKernelEx(&cfg, scatter_scores, idx, out, n);
}